// round 8
// baseline (speedup 1.0000x reference)
#include <cuda_runtime.h>

#define N_PTS   524288            // = 1 << 19
#define PT_BITS 19
#define TBITS   19
#define TMASK   ((1u << TBITS) - 1u)
#define BLOCK   768
#define PPB     384
#define AS      97                // activation row stride (floats), odd -> conflict-free
#define W_FLOATS 13576
#define SMEM_FLOATS (W_FLOATS + PPB * AS)
#define SMEM_BYTES  (SMEM_FLOATS * 4)

// Feature-major hash-encode scratch: g_enc[f * N_PTS + pt], f in [0,32)
__device__ float g_enc[32u * N_PTS];

// Packed dual-FMA on float2 (sm_103a f32x2 pipe)
__device__ __forceinline__ float2 ffma2(float2 a, float2 b, float2 c) {
    float2 d;
    asm("fma.rn.f32x2 %0, %1, %2, %3;"
        : "=l"(reinterpret_cast<unsigned long long&>(d))
        : "l"(reinterpret_cast<unsigned long long&>(a)),
          "l"(reinterpret_cast<unsigned long long&>(b)),
          "l"(reinterpret_cast<unsigned long long&>(c)));
    return d;
}

__constant__ float c_scale[16] = {
    16.f, 21.f, 27.f, 36.f, 48.f, 64.f, 84.f, 111.f,
    147.f, 194.f, 256.f, 337.f, 445.f, 588.f, 776.f, 1024.f
};

// ===================== Kernel A: hash-grid encode =====================
__global__ __launch_bounds__(256) void encode_kernel(
    const float* __restrict__ pos, const float2* __restrict__ tab)
{
    const unsigned g  = blockIdx.x * 256u + threadIdx.x;
    const int      l  = (int)(g >> PT_BITS);       // 0..15
    const unsigned pt = g & (N_PTS - 1u);

    const float px = pos[3 * pt], py = pos[3 * pt + 1], pz = pos[3 * pt + 2];
    const float sc = c_scale[l];
    const float sx = px * sc, sy = py * sc, sz = pz * sc;
    const float fx = floorf(sx), fy = floorf(sy), fz = floorf(sz);
    const float ox = sx - fx, oy = sy - fy, oz = sz - fz;
    const unsigned hx0 = (unsigned)(int)fx;                 // x prime = 1
    const unsigned hx1 = (unsigned)(int)ceilf(sx);
    const unsigned hy0 = (unsigned)(int)fy * 2654435761u;
    const unsigned hy1 = (unsigned)(int)ceilf(sy) * 2654435761u;
    const unsigned hz0 = (unsigned)(int)fz * 805459861u;
    const unsigned hz1 = (unsigned)(int)ceilf(sz) * 805459861u;
    const unsigned lvl = ((unsigned)l) << TBITS;
    const float wx0 = 1.f - ox, wy0 = 1.f - oy, wz0 = 1.f - oz;

    float2 a = make_float2(0.f, 0.f);
    #pragma unroll
    for (int p = 0; p < 4; p++) {
        const unsigned hyz = ((p & 1) ? hy1 : hy0) ^ ((p & 2) ? hz1 : hz0);
        const unsigned i0 = (hx0 ^ hyz) & TMASK;
        const unsigned i1 = (hx1 ^ hyz) & TMASK;
        const float4 q = __ldg((const float4*)(tab + ((i0 & ~1u) + lvl)));
        const float2 lo = make_float2(q.x, q.y);
        const float2 hi = make_float2(q.z, q.w);
        float2 e0 = (i0 & 1u) ? hi : lo;
        float2 e1;
        if (i1 == (i0 ^ 1u)) {
            e1 = (i0 & 1u) ? lo : hi;
        } else {
            e1 = __ldg(&tab[i1 + lvl]);
        }
        const float wyz = ((p & 1) ? oy : wy0) * ((p & 2) ? oz : wz0);
        const float w0f = wx0 * wyz, w1f = ox * wyz;
        a = ffma2(make_float2(w0f, w0f), e0, a);
        a = ffma2(make_float2(w1f, w1f), e1, a);
    }
    g_enc[(2u * l)     * (unsigned)N_PTS + pt] = a.x;
    g_enc[(2u * l + 1) * (unsigned)N_PTS + pt] = a.y;
}

// ===================== Kernel B: MLP + heads =====================
__global__ __launch_bounds__(BLOCK, 1) void mlp_kernel(
    const float* __restrict__ dir,
    const float* __restrict__ w0, const float* __restrict__ b0,
    const float* __restrict__ w1, const float* __restrict__ b1,
    const float* __restrict__ w2, const float* __restrict__ b2,
    const float* __restrict__ wr, const float* __restrict__ br,
    const float* __restrict__ wc, const float* __restrict__ bc,
    const float* __restrict__ wd, const float* __restrict__ bd,
    float* __restrict__ out)
{
    extern __shared__ float sm[];
    float4* s_w0  = (float4*)(sm + 0);      // [64 out][8  q]
    float4* s_w1  = (float4*)(sm + 2048);   // [64 out][16 q]
    float4* s_w2  = (float4*)(sm + 6144);   // [64 out][16 q]
    float4* s_wrb = (float4*)(sm + 10240);  // [32 out][16 q]  (wr rows 27..90)
    float4* s_wrd = (float4*)(sm + 12288);  // [32 out][7  q]  (wr rows 0..26 + pad)
    float4* s_wc  = (float4*)(sm + 13184);  // [3][8 q]
    float4* s_wd  = (float4*)(sm + 13280);  // [16 q]
    float*  s_b0  = sm + 13344;
    float*  s_b1  = sm + 13408;
    float*  s_b2  = sm + 13472;
    float*  s_br  = sm + 13536;
    float*  s_bc  = sm + 13568;
    float*  s_bd  = sm + 13572;
    float*  buf   = sm + W_FLOATS;          // [PPB][97]

    const int t = threadIdx.x;
    for (int k = t; k < 64 * 8; k += BLOCK) {
        int o = k >> 3, q = k & 7;
        s_w0[k] = make_float4(w0[(4*q  )*64 + o], w0[(4*q+1)*64 + o],
                              w0[(4*q+2)*64 + o], w0[(4*q+3)*64 + o]);
    }
    for (int k = t; k < 64 * 16; k += BLOCK) {
        int o = k >> 4, q = k & 15;
        s_w1[k] = make_float4(w1[(4*q  )*64 + o], w1[(4*q+1)*64 + o],
                              w1[(4*q+2)*64 + o], w1[(4*q+3)*64 + o]);
        s_w2[k] = make_float4(w2[(4*q  )*64 + o], w2[(4*q+1)*64 + o],
                              w2[(4*q+2)*64 + o], w2[(4*q+3)*64 + o]);
    }
    for (int k = t; k < 32 * 16; k += BLOCK) {
        int o = k >> 4, q = k & 15;
        s_wrb[k] = make_float4(wr[(27+4*q  )*32 + o], wr[(27+4*q+1)*32 + o],
                               wr[(27+4*q+2)*32 + o], wr[(27+4*q+3)*32 + o]);
    }
    for (int k = t; k < 32 * 7; k += BLOCK) {
        int o = k / 7, q = k % 7;
        float a = wr[(4*q  )*32 + o];
        float b = wr[(4*q+1)*32 + o];
        float c = wr[(4*q+2)*32 + o];
        float d = (q == 6) ? 0.f : wr[(4*q+3)*32 + o];
        s_wrd[k] = make_float4(a, b, c, d);
    }
    for (int k = t; k < 3 * 8; k += BLOCK) {
        int c = k >> 3, q = k & 7;
        s_wc[k] = make_float4(wc[(4*q  )*3 + c], wc[(4*q+1)*3 + c],
                              wc[(4*q+2)*3 + c], wc[(4*q+3)*3 + c]);
    }
    for (int k = t; k < 16; k += BLOCK)
        s_wd[k] = make_float4(wd[4*k], wd[4*k+1], wd[4*k+2], wd[4*k+3]);
    for (int k = t; k < 64; k += BLOCK) { s_b0[k] = b0[k]; s_b1[k] = b1[k]; s_b2[k] = b2[k]; }
    for (int k = t; k < 32; k += BLOCK) s_br[k] = br[k];
    if (t < 3) s_bc[t] = bc[t];
    if (t == 0) s_bd[0] = bd[0];

    const int ib = blockIdx.x * PPB;

    // ---- Stage enc from scratch: coalesced LDG -> conflict-free STS ----
    for (int k = t; k < 32 * PPB; k += BLOCK) {
        const int f = k / PPB, p = k - f * PPB;
        int gp = ib + p; if (gp >= N_PTS) gp = N_PTS - 1;
        buf[p * AS + f] = g_enc[(unsigned)f * N_PTS + (unsigned)gp];
    }

    // ---- Direction encode: 2 threads per point -> row[64..91] ----
    {
        const int pt = (t < PPB) ? t : (t - PPB);
        const int hf = (t >= PPB);
        int i = ib + pt; if (i >= N_PTS) i = N_PTS - 1;
        float* row = buf + pt * AS;
        const float fr[4] = {1.f, 2.5198421f, 6.3496042f, 16.f};
        if (hf == 0) {
            const float dx = dir[3 * i], dy = dir[3 * i + 1];
            const float tx = 6.2831855f * dx, ty = 6.2831855f * dy;
            #pragma unroll
            for (int k = 0; k < 4; k++) {
                float s, c;
                sincosf(tx * fr[k], &s, &c);
                row[64 + k] = s; row[64 + 12 + k] = c;
                sincosf(ty * fr[k], &s, &c);
                row[64 + 4 + k] = s; row[64 + 16 + k] = c;
            }
        } else {
            const float dx = dir[3 * i], dy = dir[3 * i + 1], dz = dir[3 * i + 2];
            const float tz = 6.2831855f * dz;
            #pragma unroll
            for (int k = 0; k < 4; k++) {
                float s, c;
                sincosf(tz * fr[k], &s, &c);
                row[64 + 8 + k] = s; row[64 + 20 + k] = c;
            }
            row[64 + 24] = dx; row[64 + 25] = dy; row[64 + 26] = dz;
            row[64 + 27] = 0.f;
        }
    }
    __syncthreads();

    // ================= MLP: warp-uniform quarter, 2 points/lane =============
    const int w    = t >> 5, lane = t & 31;
    const int qt   = w & 3;                 // output quarter (warp-uniform)
    const int pg   = w >> 2;                // point group 0..5
    const int p0   = pg * 64 + lane;
    const int p1   = p0 + 32;
    float* r0 = buf + p0 * AS;
    float* r1 = buf + p1 * AS;

    float acc0[16], acc1[16];

    // ---------------- Layer 0: 32 -> 64, relu (8-wide k chunks) ----------
    #pragma unroll
    for (int o = 0; o < 16; o++) { acc0[o] = 0.f; acc1[o] = 0.f; }
    #pragma unroll
    for (int c = 0; c < 4; c++) {
        float a0[8], a1[8];
        #pragma unroll
        for (int k = 0; k < 8; k++) { a0[k] = r0[8*c + k]; a1[k] = r1[8*c + k]; }
        #pragma unroll
        for (int o = 0; o < 16; o++) {
            const float4* wv = s_w0 + (qt * 16 + o) * 8 + 2 * c;
            const float4 v0 = wv[0], v1 = wv[1];
            float2 t0 = make_float2(0.f, 0.f), t1 = make_float2(0.f, 0.f);
            t0 = ffma2(make_float2(a0[0], a0[1]), make_float2(v0.x, v0.y), t0);
            t0 = ffma2(make_float2(a0[2], a0[3]), make_float2(v0.z, v0.w), t0);
            t0 = ffma2(make_float2(a0[4], a0[5]), make_float2(v1.x, v1.y), t0);
            t0 = ffma2(make_float2(a0[6], a0[7]), make_float2(v1.z, v1.w), t0);
            t1 = ffma2(make_float2(a1[0], a1[1]), make_float2(v0.x, v0.y), t1);
            t1 = ffma2(make_float2(a1[2], a1[3]), make_float2(v0.z, v0.w), t1);
            t1 = ffma2(make_float2(a1[4], a1[5]), make_float2(v1.x, v1.y), t1);
            t1 = ffma2(make_float2(a1[6], a1[7]), make_float2(v1.z, v1.w), t1);
            acc0[o] += t0.x + t0.y;
            acc1[o] += t1.x + t1.y;
        }
    }
    __syncthreads();
    #pragma unroll
    for (int o = 0; o < 16; o++) {
        const int og = qt * 16 + o;
        r0[og] = fmaxf(acc0[o] + s_b0[og], 0.f);
        r1[og] = fmaxf(acc1[o] + s_b0[og], 0.f);
    }
    __syncthreads();

    // ---------------- Layer 1: 64 -> 64, relu ----------------
    #pragma unroll
    for (int o = 0; o < 16; o++) { acc0[o] = 0.f; acc1[o] = 0.f; }
    #pragma unroll
    for (int c = 0; c < 8; c++) {
        float a0[8], a1[8];
        #pragma unroll
        for (int k = 0; k < 8; k++) { a0[k] = r0[8*c + k]; a1[k] = r1[8*c + k]; }
        #pragma unroll
        for (int o = 0; o < 16; o++) {
            const float4* wv = s_w1 + (qt * 16 + o) * 16 + 2 * c;
            const float4 v0 = wv[0], v1 = wv[1];
            float2 t0 = make_float2(0.f, 0.f), t1 = make_float2(0.f, 0.f);
            t0 = ffma2(make_float2(a0[0], a0[1]), make_float2(v0.x, v0.y), t0);
            t0 = ffma2(make_float2(a0[2], a0[3]), make_float2(v0.z, v0.w), t0);
            t0 = ffma2(make_float2(a0[4], a0[5]), make_float2(v1.x, v1.y), t0);
            t0 = ffma2(make_float2(a0[6], a0[7]), make_float2(v1.z, v1.w), t0);
            t1 = ffma2(make_float2(a1[0], a1[1]), make_float2(v0.x, v0.y), t1);
            t1 = ffma2(make_float2(a1[2], a1[3]), make_float2(v0.z, v0.w), t1);
            t1 = ffma2(make_float2(a1[4], a1[5]), make_float2(v1.x, v1.y), t1);
            t1 = ffma2(make_float2(a1[6], a1[7]), make_float2(v1.z, v1.w), t1);
            acc0[o] += t0.x + t0.y;
            acc1[o] += t1.x + t1.y;
        }
    }
    __syncthreads();
    #pragma unroll
    for (int o = 0; o < 16; o++) {
        const int og = qt * 16 + o;
        r0[og] = fmaxf(acc0[o] + s_b1[og], 0.f);
        r1[og] = fmaxf(acc1[o] + s_b1[og], 0.f);
    }
    __syncthreads();

    // ---------------- Layer 2: 64 -> 64, linear (base) ----------------
    #pragma unroll
    for (int o = 0; o < 16; o++) { acc0[o] = 0.f; acc1[o] = 0.f; }
    #pragma unroll
    for (int c = 0; c < 8; c++) {
        float a0[8], a1[8];
        #pragma unroll
        for (int k = 0; k < 8; k++) { a0[k] = r0[8*c + k]; a1[k] = r1[8*c + k]; }
        #pragma unroll
        for (int o = 0; o < 16; o++) {
            const float4* wv = s_w2 + (qt * 16 + o) * 16 + 2 * c;
            const float4 v0 = wv[0], v1 = wv[1];
            float2 t0 = make_float2(0.f, 0.f), t1 = make_float2(0.f, 0.f);
            t0 = ffma2(make_float2(a0[0], a0[1]), make_float2(v0.x, v0.y), t0);
            t0 = ffma2(make_float2(a0[2], a0[3]), make_float2(v0.z, v0.w), t0);
            t0 = ffma2(make_float2(a0[4], a0[5]), make_float2(v1.x, v1.y), t0);
            t0 = ffma2(make_float2(a0[6], a0[7]), make_float2(v1.z, v1.w), t0);
            t1 = ffma2(make_float2(a1[0], a1[1]), make_float2(v0.x, v0.y), t1);
            t1 = ffma2(make_float2(a1[2], a1[3]), make_float2(v0.z, v0.w), t1);
            t1 = ffma2(make_float2(a1[4], a1[5]), make_float2(v1.x, v1.y), t1);
            t1 = ffma2(make_float2(a1[6], a1[7]), make_float2(v1.z, v1.w), t1);
            acc0[o] += t0.x + t0.y;
            acc1[o] += t1.x + t1.y;
        }
    }
    __syncthreads();
    #pragma unroll
    for (int o = 0; o < 16; o++) {
        const int og = qt * 16 + o;
        r0[og] = acc0[o] + s_b2[og];
        r1[og] = acc1[o] + s_b2[og];
    }
    __syncthreads();
    // row[0..63] = bp, row[64..91] = dvec

    // ---------------- RGB head: 8 outputs per warp-quarter, 2 points --------
    float h80[8], h81[8];
    #pragma unroll
    for (int o = 0; o < 8; o++) {
        const int og = qt * 8 + o;
        h80[o] = s_br[og]; h81[o] = s_br[og];
    }
    #pragma unroll
    for (int c = 0; c < 7; c++) {
        float d0[4], d1[4];
        #pragma unroll
        for (int k = 0; k < 4; k++) { d0[k] = r0[64 + 4*c + k]; d1[k] = r1[64 + 4*c + k]; }
        #pragma unroll
        for (int o = 0; o < 8; o++) {
            const float4 v = s_wrd[(qt * 8 + o) * 7 + c];
            h80[o] = fmaf(d0[0], v.x, fmaf(d0[1], v.y, fmaf(d0[2], v.z, fmaf(d0[3], v.w, h80[o]))));
            h81[o] = fmaf(d1[0], v.x, fmaf(d1[1], v.y, fmaf(d1[2], v.z, fmaf(d1[3], v.w, h81[o]))));
        }
    }
    #pragma unroll
    for (int c = 0; c < 8; c++) {
        float a0[8], a1[8];
        #pragma unroll
        for (int k = 0; k < 8; k++) { a0[k] = r0[8*c + k]; a1[k] = r1[8*c + k]; }
        #pragma unroll
        for (int o = 0; o < 8; o++) {
            const float4* wv = s_wrb + (qt * 8 + o) * 16 + 2 * c;
            const float4 v0 = wv[0], v1 = wv[1];
            float2 t0 = make_float2(0.f, 0.f), t1 = make_float2(0.f, 0.f);
            t0 = ffma2(make_float2(a0[0], a0[1]), make_float2(v0.x, v0.y), t0);
            t0 = ffma2(make_float2(a0[2], a0[3]), make_float2(v0.z, v0.w), t0);
            t0 = ffma2(make_float2(a0[4], a0[5]), make_float2(v1.x, v1.y), t0);
            t0 = ffma2(make_float2(a0[6], a0[7]), make_float2(v1.z, v1.w), t0);
            t1 = ffma2(make_float2(a1[0], a1[1]), make_float2(v0.x, v0.y), t1);
            t1 = ffma2(make_float2(a1[2], a1[3]), make_float2(v0.z, v0.w), t1);
            t1 = ffma2(make_float2(a1[4], a1[5]), make_float2(v1.x, v1.y), t1);
            t1 = ffma2(make_float2(a1[6], a1[7]), make_float2(v1.z, v1.w), t1);
            h80[o] += t0.x + t0.y;
            h81[o] += t1.x + t1.y;
        }
    }
    __syncthreads();
    #pragma unroll
    for (int o = 0; o < 8; o++) {
        const int og = qt * 8 + o;
        r0[64 + og] = h80[o];
        r1[64 + og] = h81[o];
    }
    __syncthreads();

    if (qt == 0) {
        #pragma unroll
        for (int s = 0; s < 2; s++) {
            float* r = s ? r1 : r0;
            const int ii = ib + (s ? p1 : p0);
            float rg[32];
            #pragma unroll
            for (int k = 0; k < 32; k++) rg[k] = r[64 + k];
            if (ii < N_PTS) {
                #pragma unroll
                for (int c = 0; c < 3; c++) {
                    float a = s_bc[c];
                    const float4* wcrow = s_wc + c * 8;
                    #pragma unroll
                    for (int q = 0; q < 8; q++) {
                        const float4 v = wcrow[q];
                        a = fmaf(rg[4*q],   v.x, a);
                        a = fmaf(rg[4*q+1], v.y, a);
                        a = fmaf(rg[4*q+2], v.z, a);
                        a = fmaf(rg[4*q+3], v.w, a);
                    }
                    out[4 * ii + c] = 1.f / (1.f + expf(-a));
                }
            }
        }
    } else if (qt == 1) {
        #pragma unroll
        for (int s = 0; s < 2; s++) {
            float* r = s ? r1 : r0;
            const int ii = ib + (s ? p1 : p0);
            if (ii < N_PTS) {
                float2 a2 = make_float2(0.f, 0.f);
                #pragma unroll
                for (int q = 0; q < 16; q++) {
                    const float4 v = s_wd[q];
                    a2 = ffma2(make_float2(r[4*q],   r[4*q+1]), make_float2(v.x, v.y), a2);
                    a2 = ffma2(make_float2(r[4*q+2], r[4*q+3]), make_float2(v.z, v.w), a2);
                }
                const float xd = a2.x + a2.y + s_bd[0];
                out[4 * ii + 3] = fmaxf(xd, 0.f) + log1pf(expf(-fabsf(xd)));
            }
        }
    }
}

extern "C" void kernel_launch(void* const* d_in, const int* in_sizes, int n_in,
                              void* d_out, int out_size) {
    (void)in_sizes; (void)n_in; (void)out_size;
    const float*  pos = (const float*)d_in[0];
    const float*  dir = (const float*)d_in[1];
    const float2* tab = (const float2*)d_in[2];
    const float *w0 = (const float*)d_in[3],  *b0 = (const float*)d_in[4];
    const float *w1 = (const float*)d_in[5],  *b1 = (const float*)d_in[6];
    const float *w2 = (const float*)d_in[7],  *b2 = (const float*)d_in[8];
    const float *wr = (const float*)d_in[9],  *br = (const float*)d_in[10];
    const float *wc = (const float*)d_in[11], *bc = (const float*)d_in[12];
    const float *wd = (const float*)d_in[13], *bd = (const float*)d_in[14];
    float* out = (float*)d_out;

    encode_kernel<<<(16 * N_PTS) / 256, 256>>>(pos, tab);

    cudaFuncSetAttribute(mlp_kernel,
                         cudaFuncAttributeMaxDynamicSharedMemorySize, SMEM_BYTES);
    const int grid = (N_PTS + PPB - 1) / PPB;   // 1366 (tail block guarded)
    mlp_kernel<<<grid, BLOCK, SMEM_BYTES>>>(
        dir, w0, b0, w1, b1, w2, b2, wr, br, wc, bc, wd, bd, out);
}

// round 9
// speedup vs baseline: 1.1373x; 1.1373x over previous
#include <cuda_runtime.h>

#define N_PTS   524288            // = 1 << 19
#define PT_BITS 19
#define TBITS   19
#define TMASK   ((1u << TBITS) - 1u)
#define BLOCK   256
#define PPB     128
#define AS      100               // row stride: 100 ≡ 4 (mod 32) -> LDS.128 lanes tile banks
#define W_FLOATS 13576
#define SMEM_FLOATS (W_FLOATS + PPB * AS)
#define SMEM_BYTES  (SMEM_FLOATS * 4)

// Feature-major hash-encode scratch: g_enc[f * N_PTS + pt], f in [0,32)
__device__ float g_enc[32u * N_PTS];

// Packed dual-FMA on float2 (sm_103a f32x2 pipe)
__device__ __forceinline__ float2 ffma2(float2 a, float2 b, float2 c) {
    float2 d;
    asm("fma.rn.f32x2 %0, %1, %2, %3;"
        : "=l"(reinterpret_cast<unsigned long long&>(d))
        : "l"(reinterpret_cast<unsigned long long&>(a)),
          "l"(reinterpret_cast<unsigned long long&>(b)),
          "l"(reinterpret_cast<unsigned long long&>(c)));
    return d;
}

__constant__ float c_scale[16] = {
    16.f, 21.f, 27.f, 36.f, 48.f, 64.f, 84.f, 111.f,
    147.f, 194.f, 256.f, 337.f, 445.f, 588.f, 776.f, 1024.f
};

// ===================== Kernel A: hash-grid encode =====================
__global__ __launch_bounds__(256) void encode_kernel(
    const float* __restrict__ pos, const float2* __restrict__ tab)
{
    const unsigned g  = blockIdx.x * 256u + threadIdx.x;
    const int      l  = (int)(g >> PT_BITS);       // 0..15
    const unsigned pt = g & (N_PTS - 1u);

    const float px = pos[3 * pt], py = pos[3 * pt + 1], pz = pos[3 * pt + 2];
    const float sc = c_scale[l];
    const float sx = px * sc, sy = py * sc, sz = pz * sc;
    const float fx = floorf(sx), fy = floorf(sy), fz = floorf(sz);
    const float ox = sx - fx, oy = sy - fy, oz = sz - fz;
    const unsigned hx0 = (unsigned)(int)fx;                 // x prime = 1
    const unsigned hx1 = (unsigned)(int)ceilf(sx);
    const unsigned hy0 = (unsigned)(int)fy * 2654435761u;
    const unsigned hy1 = (unsigned)(int)ceilf(sy) * 2654435761u;
    const unsigned hz0 = (unsigned)(int)fz * 805459861u;
    const unsigned hz1 = (unsigned)(int)ceilf(sz) * 805459861u;
    const unsigned lvl = ((unsigned)l) << TBITS;
    const float wx0 = 1.f - ox, wy0 = 1.f - oy, wz0 = 1.f - oz;

    float2 a = make_float2(0.f, 0.f);
    #pragma unroll
    for (int p = 0; p < 4; p++) {
        const unsigned hyz = ((p & 1) ? hy1 : hy0) ^ ((p & 2) ? hz1 : hz0);
        const unsigned i0 = (hx0 ^ hyz) & TMASK;
        const unsigned i1 = (hx1 ^ hyz) & TMASK;
        const float4 q = __ldg((const float4*)(tab + ((i0 & ~1u) + lvl)));
        const float2 lo = make_float2(q.x, q.y);
        const float2 hi = make_float2(q.z, q.w);
        float2 e0 = (i0 & 1u) ? hi : lo;
        float2 e1;
        if (i1 == (i0 ^ 1u)) {
            e1 = (i0 & 1u) ? lo : hi;
        } else {
            e1 = __ldg(&tab[i1 + lvl]);
        }
        const float wyz = ((p & 1) ? oy : wy0) * ((p & 2) ? oz : wz0);
        const float w0f = wx0 * wyz, w1f = ox * wyz;
        a = ffma2(make_float2(w0f, w0f), e0, a);
        a = ffma2(make_float2(w1f, w1f), e1, a);
    }
    g_enc[(2u * l)     * (unsigned)N_PTS + pt] = a.x;
    g_enc[(2u * l + 1) * (unsigned)N_PTS + pt] = a.y;
}

// ===================== Kernel B: MLP + heads =====================
__global__ __launch_bounds__(BLOCK, 2) void mlp_kernel(
    const float* __restrict__ dir,
    const float* __restrict__ w0, const float* __restrict__ b0,
    const float* __restrict__ w1, const float* __restrict__ b1,
    const float* __restrict__ w2, const float* __restrict__ b2,
    const float* __restrict__ wr, const float* __restrict__ br,
    const float* __restrict__ wc, const float* __restrict__ bc,
    const float* __restrict__ wd, const float* __restrict__ bd,
    float* __restrict__ out)
{
    extern __shared__ float sm[];
    float4* s_w0  = (float4*)(sm + 0);      // [64 out][8  q]
    float4* s_w1  = (float4*)(sm + 2048);   // [64 out][16 q]
    float4* s_w2  = (float4*)(sm + 6144);   // [64 out][16 q]
    float4* s_wrb = (float4*)(sm + 10240);  // [32 out][16 q]  (wr rows 27..90)
    float4* s_wrd = (float4*)(sm + 12288);  // [32 out][7  q]  (wr rows 0..26 + pad)
    float4* s_wc  = (float4*)(sm + 13184);  // [3][8 q]
    float4* s_wd  = (float4*)(sm + 13280);  // [16 q]
    float*  s_b0  = sm + 13344;
    float*  s_b1  = sm + 13408;
    float*  s_b2  = sm + 13472;
    float*  s_br  = sm + 13536;
    float*  s_bc  = sm + 13568;
    float*  s_bd  = sm + 13572;
    float*  buf   = sm + W_FLOATS;          // [128][100]

    const int t = threadIdx.x;
    for (int k = t; k < 64 * 8; k += BLOCK) {
        int o = k >> 3, q = k & 7;
        s_w0[k] = make_float4(w0[(4*q  )*64 + o], w0[(4*q+1)*64 + o],
                              w0[(4*q+2)*64 + o], w0[(4*q+3)*64 + o]);
    }
    for (int k = t; k < 64 * 16; k += BLOCK) {
        int o = k >> 4, q = k & 15;
        s_w1[k] = make_float4(w1[(4*q  )*64 + o], w1[(4*q+1)*64 + o],
                              w1[(4*q+2)*64 + o], w1[(4*q+3)*64 + o]);
        s_w2[k] = make_float4(w2[(4*q  )*64 + o], w2[(4*q+1)*64 + o],
                              w2[(4*q+2)*64 + o], w2[(4*q+3)*64 + o]);
    }
    for (int k = t; k < 32 * 16; k += BLOCK) {
        int o = k >> 4, q = k & 15;
        s_wrb[k] = make_float4(wr[(27+4*q  )*32 + o], wr[(27+4*q+1)*32 + o],
                               wr[(27+4*q+2)*32 + o], wr[(27+4*q+3)*32 + o]);
    }
    for (int k = t; k < 32 * 7; k += BLOCK) {
        int o = k / 7, q = k % 7;
        float a = wr[(4*q  )*32 + o];
        float b = wr[(4*q+1)*32 + o];
        float c = wr[(4*q+2)*32 + o];
        float d = (q == 6) ? 0.f : wr[(4*q+3)*32 + o];
        s_wrd[k] = make_float4(a, b, c, d);
    }
    for (int k = t; k < 3 * 8; k += BLOCK) {
        int c = k >> 3, q = k & 7;
        s_wc[k] = make_float4(wc[(4*q  )*3 + c], wc[(4*q+1)*3 + c],
                              wc[(4*q+2)*3 + c], wc[(4*q+3)*3 + c]);
    }
    for (int k = t; k < 16; k += BLOCK)
        s_wd[k] = make_float4(wd[4*k], wd[4*k+1], wd[4*k+2], wd[4*k+3]);
    for (int k = t; k < 64; k += BLOCK) { s_b0[k] = b0[k]; s_b1[k] = b1[k]; s_b2[k] = b2[k]; }
    for (int k = t; k < 32; k += BLOCK) s_br[k] = br[k];
    if (t < 3) s_bc[t] = bc[t];
    if (t == 0) s_bd[0] = bd[0];

    const int ib = blockIdx.x * PPB;

    // ---- Stage enc: coalesced LDG x4 -> one STS.128 (lanes tile banks) ----
    for (int k = t; k < 8 * PPB; k += BLOCK) {
        const int fg = k >> 7;            // 0..7 -> f = 4*fg
        const int p  = k & (PPB - 1);
        const unsigned gp = (unsigned)(ib + p);
        const int f = 4 * fg;
        float4 v;
        v.x = g_enc[(unsigned)(f    ) * N_PTS + gp];
        v.y = g_enc[(unsigned)(f + 1) * N_PTS + gp];
        v.z = g_enc[(unsigned)(f + 2) * N_PTS + gp];
        v.w = g_enc[(unsigned)(f + 3) * N_PTS + gp];
        *(float4*)(buf + p * AS + f) = v;
    }

    // ---- Direction encode: 2 threads per point -> row[64..91] ----
    {
        const int pt = t & (PPB - 1);
        const int hf = t >> 7;
        const int i  = ib + pt;
        float* row = buf + pt * AS;
        const float fr[4] = {1.f, 2.5198421f, 6.3496042f, 16.f};
        if (hf == 0) {
            const float dx = dir[3 * i], dy = dir[3 * i + 1];
            const float tx = 6.2831855f * dx, ty = 6.2831855f * dy;
            #pragma unroll
            for (int k = 0; k < 4; k++) {
                float s, c;
                sincosf(tx * fr[k], &s, &c);
                row[64 + k] = s; row[64 + 12 + k] = c;
                sincosf(ty * fr[k], &s, &c);
                row[64 + 4 + k] = s; row[64 + 16 + k] = c;
            }
        } else {
            const float dx = dir[3 * i], dy = dir[3 * i + 1], dz = dir[3 * i + 2];
            const float tz = 6.2831855f * dz;
            #pragma unroll
            for (int k = 0; k < 4; k++) {
                float s, c;
                sincosf(tz * fr[k], &s, &c);
                row[64 + 8 + k] = s; row[64 + 20 + k] = c;
            }
            row[64 + 24] = dx; row[64 + 25] = dy; row[64 + 26] = dz;
            row[64 + 27] = 0.f;
        }
    }
    __syncthreads();

    // ================= MLP: warp-uniform quarter, 2 points/lane =============
    const int w    = t >> 5, lane = t & 31;
    const int qt   = w & 3;
    const int pg   = w >> 2;
    const int p0   = pg * 64 + lane;
    const int p1   = p0 + 32;
    float* r0 = buf + p0 * AS;
    float* r1 = buf + p1 * AS;

    float2 acc0[16], acc1[16];

    // ---------------- Layer 0: 32 -> 64, relu ----------------
    #pragma unroll
    for (int o = 0; o < 16; o++) { acc0[o] = make_float2(0.f,0.f); acc1[o] = make_float2(0.f,0.f); }
    #pragma unroll
    for (int c = 0; c < 4; c++) {
        const float4 qa0 = *(const float4*)(r0 + 8*c);
        const float4 qb0 = *(const float4*)(r0 + 8*c + 4);
        const float4 qa1 = *(const float4*)(r1 + 8*c);
        const float4 qb1 = *(const float4*)(r1 + 8*c + 4);
        const float2 a00 = make_float2(qa0.x,qa0.y), a01 = make_float2(qa0.z,qa0.w);
        const float2 a02 = make_float2(qb0.x,qb0.y), a03 = make_float2(qb0.z,qb0.w);
        const float2 a10 = make_float2(qa1.x,qa1.y), a11 = make_float2(qa1.z,qa1.w);
        const float2 a12 = make_float2(qb1.x,qb1.y), a13 = make_float2(qb1.z,qb1.w);
        #pragma unroll
        for (int o = 0; o < 16; o++) {
            const float4* wv = s_w0 + (qt * 16 + o) * 8 + 2 * c;
            const float4 v0 = wv[0], v1 = wv[1];
            const float2 w0f = make_float2(v0.x,v0.y), w1f = make_float2(v0.z,v0.w);
            const float2 w2f = make_float2(v1.x,v1.y), w3f = make_float2(v1.z,v1.w);
            acc0[o] = ffma2(a00, w0f, acc0[o]); acc0[o] = ffma2(a01, w1f, acc0[o]);
            acc0[o] = ffma2(a02, w2f, acc0[o]); acc0[o] = ffma2(a03, w3f, acc0[o]);
            acc1[o] = ffma2(a10, w0f, acc1[o]); acc1[o] = ffma2(a11, w1f, acc1[o]);
            acc1[o] = ffma2(a12, w2f, acc1[o]); acc1[o] = ffma2(a13, w3f, acc1[o]);
        }
    }
    __syncthreads();
    #pragma unroll
    for (int g4 = 0; g4 < 4; g4++) {
        float4 s0, s1;
        const int ob = qt * 16 + 4 * g4;
        s0.x = fmaxf(acc0[4*g4  ].x + acc0[4*g4  ].y + s_b0[ob  ], 0.f);
        s0.y = fmaxf(acc0[4*g4+1].x + acc0[4*g4+1].y + s_b0[ob+1], 0.f);
        s0.z = fmaxf(acc0[4*g4+2].x + acc0[4*g4+2].y + s_b0[ob+2], 0.f);
        s0.w = fmaxf(acc0[4*g4+3].x + acc0[4*g4+3].y + s_b0[ob+3], 0.f);
        s1.x = fmaxf(acc1[4*g4  ].x + acc1[4*g4  ].y + s_b0[ob  ], 0.f);
        s1.y = fmaxf(acc1[4*g4+1].x + acc1[4*g4+1].y + s_b0[ob+1], 0.f);
        s1.z = fmaxf(acc1[4*g4+2].x + acc1[4*g4+2].y + s_b0[ob+2], 0.f);
        s1.w = fmaxf(acc1[4*g4+3].x + acc1[4*g4+3].y + s_b0[ob+3], 0.f);
        *(float4*)(r0 + ob) = s0;
        *(float4*)(r1 + ob) = s1;
    }
    __syncthreads();

    // ---------------- Layer 1: 64 -> 64, relu ----------------
    #pragma unroll
    for (int o = 0; o < 16; o++) { acc0[o] = make_float2(0.f,0.f); acc1[o] = make_float2(0.f,0.f); }
    #pragma unroll
    for (int c = 0; c < 8; c++) {
        const float4 qa0 = *(const float4*)(r0 + 8*c);
        const float4 qb0 = *(const float4*)(r0 + 8*c + 4);
        const float4 qa1 = *(const float4*)(r1 + 8*c);
        const float4 qb1 = *(const float4*)(r1 + 8*c + 4);
        const float2 a00 = make_float2(qa0.x,qa0.y), a01 = make_float2(qa0.z,qa0.w);
        const float2 a02 = make_float2(qb0.x,qb0.y), a03 = make_float2(qb0.z,qb0.w);
        const float2 a10 = make_float2(qa1.x,qa1.y), a11 = make_float2(qa1.z,qa1.w);
        const float2 a12 = make_float2(qb1.x,qb1.y), a13 = make_float2(qb1.z,qb1.w);
        #pragma unroll
        for (int o = 0; o < 16; o++) {
            const float4* wv = s_w1 + (qt * 16 + o) * 16 + 2 * c;
            const float4 v0 = wv[0], v1 = wv[1];
            const float2 w0f = make_float2(v0.x,v0.y), w1f = make_float2(v0.z,v0.w);
            const float2 w2f = make_float2(v1.x,v1.y), w3f = make_float2(v1.z,v1.w);
            acc0[o] = ffma2(a00, w0f, acc0[o]); acc0[o] = ffma2(a01, w1f, acc0[o]);
            acc0[o] = ffma2(a02, w2f, acc0[o]); acc0[o] = ffma2(a03, w3f, acc0[o]);
            acc1[o] = ffma2(a10, w0f, acc1[o]); acc1[o] = ffma2(a11, w1f, acc1[o]);
            acc1[o] = ffma2(a12, w2f, acc1[o]); acc1[o] = ffma2(a13, w3f, acc1[o]);
        }
    }
    __syncthreads();
    #pragma unroll
    for (int g4 = 0; g4 < 4; g4++) {
        float4 s0, s1;
        const int ob = qt * 16 + 4 * g4;
        s0.x = fmaxf(acc0[4*g4  ].x + acc0[4*g4  ].y + s_b1[ob  ], 0.f);
        s0.y = fmaxf(acc0[4*g4+1].x + acc0[4*g4+1].y + s_b1[ob+1], 0.f);
        s0.z = fmaxf(acc0[4*g4+2].x + acc0[4*g4+2].y + s_b1[ob+2], 0.f);
        s0.w = fmaxf(acc0[4*g4+3].x + acc0[4*g4+3].y + s_b1[ob+3], 0.f);
        s1.x = fmaxf(acc1[4*g4  ].x + acc1[4*g4  ].y + s_b1[ob  ], 0.f);
        s1.y = fmaxf(acc1[4*g4+1].x + acc1[4*g4+1].y + s_b1[ob+1], 0.f);
        s1.z = fmaxf(acc1[4*g4+2].x + acc1[4*g4+2].y + s_b1[ob+2], 0.f);
        s1.w = fmaxf(acc1[4*g4+3].x + acc1[4*g4+3].y + s_b1[ob+3], 0.f);
        *(float4*)(r0 + ob) = s0;
        *(float4*)(r1 + ob) = s1;
    }
    __syncthreads();

    // ---------------- Layer 2: 64 -> 64, linear (base) ----------------
    #pragma unroll
    for (int o = 0; o < 16; o++) { acc0[o] = make_float2(0.f,0.f); acc1[o] = make_float2(0.f,0.f); }
    #pragma unroll
    for (int c = 0; c < 8; c++) {
        const float4 qa0 = *(const float4*)(r0 + 8*c);
        const float4 qb0 = *(const float4*)(r0 + 8*c + 4);
        const float4 qa1 = *(const float4*)(r1 + 8*c);
        const float4 qb1 = *(const float4*)(r1 + 8*c + 4);
        const float2 a00 = make_float2(qa0.x,qa0.y), a01 = make_float2(qa0.z,qa0.w);
        const float2 a02 = make_float2(qb0.x,qb0.y), a03 = make_float2(qb0.z,qb0.w);
        const float2 a10 = make_float2(qa1.x,qa1.y), a11 = make_float2(qa1.z,qa1.w);
        const float2 a12 = make_float2(qb1.x,qb1.y), a13 = make_float2(qb1.z,qb1.w);
        #pragma unroll
        for (int o = 0; o < 16; o++) {
            const float4* wv = s_w2 + (qt * 16 + o) * 16 + 2 * c;
            const float4 v0 = wv[0], v1 = wv[1];
            const float2 w0f = make_float2(v0.x,v0.y), w1f = make_float2(v0.z,v0.w);
            const float2 w2f = make_float2(v1.x,v1.y), w3f = make_float2(v1.z,v1.w);
            acc0[o] = ffma2(a00, w0f, acc0[o]); acc0[o] = ffma2(a01, w1f, acc0[o]);
            acc0[o] = ffma2(a02, w2f, acc0[o]); acc0[o] = ffma2(a03, w3f, acc0[o]);
            acc1[o] = ffma2(a10, w0f, acc1[o]); acc1[o] = ffma2(a11, w1f, acc1[o]);
            acc1[o] = ffma2(a12, w2f, acc1[o]); acc1[o] = ffma2(a13, w3f, acc1[o]);
        }
    }
    __syncthreads();
    #pragma unroll
    for (int g4 = 0; g4 < 4; g4++) {
        float4 s0, s1;
        const int ob = qt * 16 + 4 * g4;
        s0.x = acc0[4*g4  ].x + acc0[4*g4  ].y + s_b2[ob  ];
        s0.y = acc0[4*g4+1].x + acc0[4*g4+1].y + s_b2[ob+1];
        s0.z = acc0[4*g4+2].x + acc0[4*g4+2].y + s_b2[ob+2];
        s0.w = acc0[4*g4+3].x + acc0[4*g4+3].y + s_b2[ob+3];
        s1.x = acc1[4*g4  ].x + acc1[4*g4  ].y + s_b2[ob  ];
        s1.y = acc1[4*g4+1].x + acc1[4*g4+1].y + s_b2[ob+1];
        s1.z = acc1[4*g4+2].x + acc1[4*g4+2].y + s_b2[ob+2];
        s1.w = acc1[4*g4+3].x + acc1[4*g4+3].y + s_b2[ob+3];
        *(float4*)(r0 + ob) = s0;
        *(float4*)(r1 + ob) = s1;
    }
    __syncthreads();
    // row[0..63] = bp, row[64..91] = dvec

    // ---------------- RGB head: 8 outputs per warp-quarter, 2 points --------
    float h80[8], h81[8];
    #pragma unroll
    for (int o = 0; o < 8; o++) {
        const int og = qt * 8 + o;
        h80[o] = s_br[og]; h81[o] = s_br[og];
    }
    #pragma unroll
    for (int c = 0; c < 7; c++) {
        const float4 d0 = *(const float4*)(r0 + 64 + 4*c);
        const float4 d1 = *(const float4*)(r1 + 64 + 4*c);
        #pragma unroll
        for (int o = 0; o < 8; o++) {
            const float4 v = s_wrd[(qt * 8 + o) * 7 + c];
            h80[o] = fmaf(d0.x, v.x, fmaf(d0.y, v.y, fmaf(d0.z, v.z, fmaf(d0.w, v.w, h80[o]))));
            h81[o] = fmaf(d1.x, v.x, fmaf(d1.y, v.y, fmaf(d1.z, v.z, fmaf(d1.w, v.w, h81[o]))));
        }
    }
    {
        float2 hb0[8], hb1[8];
        #pragma unroll
        for (int o = 0; o < 8; o++) { hb0[o] = make_float2(0.f,0.f); hb1[o] = make_float2(0.f,0.f); }
        #pragma unroll
        for (int c = 0; c < 8; c++) {
            const float4 qa0 = *(const float4*)(r0 + 8*c);
            const float4 qb0 = *(const float4*)(r0 + 8*c + 4);
            const float4 qa1 = *(const float4*)(r1 + 8*c);
            const float4 qb1 = *(const float4*)(r1 + 8*c + 4);
            const float2 a00 = make_float2(qa0.x,qa0.y), a01 = make_float2(qa0.z,qa0.w);
            const float2 a02 = make_float2(qb0.x,qb0.y), a03 = make_float2(qb0.z,qb0.w);
            const float2 a10 = make_float2(qa1.x,qa1.y), a11 = make_float2(qa1.z,qa1.w);
            const float2 a12 = make_float2(qb1.x,qb1.y), a13 = make_float2(qb1.z,qb1.w);
            #pragma unroll
            for (int o = 0; o < 8; o++) {
                const float4* wv = s_wrb + (qt * 8 + o) * 16 + 2 * c;
                const float4 v0 = wv[0], v1 = wv[1];
                const float2 w0f = make_float2(v0.x,v0.y), w1f = make_float2(v0.z,v0.w);
                const float2 w2f = make_float2(v1.x,v1.y), w3f = make_float2(v1.z,v1.w);
                hb0[o] = ffma2(a00, w0f, hb0[o]); hb0[o] = ffma2(a01, w1f, hb0[o]);
                hb0[o] = ffma2(a02, w2f, hb0[o]); hb0[o] = ffma2(a03, w3f, hb0[o]);
                hb1[o] = ffma2(a10, w0f, hb1[o]); hb1[o] = ffma2(a11, w1f, hb1[o]);
                hb1[o] = ffma2(a12, w2f, hb1[o]); hb1[o] = ffma2(a13, w3f, hb1[o]);
            }
        }
        #pragma unroll
        for (int o = 0; o < 8; o++) {
            h80[o] += hb0[o].x + hb0[o].y;
            h81[o] += hb1[o].x + hb1[o].y;
        }
    }
    __syncthreads();
    {
        float4 s0, s1, s2, s3;
        s0.x = h80[0]; s0.y = h80[1]; s0.z = h80[2]; s0.w = h80[3];
        s1.x = h80[4]; s1.y = h80[5]; s1.z = h80[6]; s1.w = h80[7];
        s2.x = h81[0]; s2.y = h81[1]; s2.z = h81[2]; s2.w = h81[3];
        s3.x = h81[4]; s3.y = h81[5]; s3.z = h81[6]; s3.w = h81[7];
        *(float4*)(r0 + 64 + qt * 8)     = s0;
        *(float4*)(r0 + 64 + qt * 8 + 4) = s1;
        *(float4*)(r1 + 64 + qt * 8)     = s2;
        *(float4*)(r1 + 64 + qt * 8 + 4) = s3;
    }
    __syncthreads();

    if (qt == 0) {
        #pragma unroll
        for (int s = 0; s < 2; s++) {
            float* r = s ? r1 : r0;
            const int ii = ib + (s ? p1 : p0);
            float rg[32];
            #pragma unroll
            for (int q = 0; q < 8; q++) {
                const float4 v = *(const float4*)(r + 64 + 4*q);
                rg[4*q] = v.x; rg[4*q+1] = v.y; rg[4*q+2] = v.z; rg[4*q+3] = v.w;
            }
            #pragma unroll
            for (int c = 0; c < 3; c++) {
                float a = s_bc[c];
                const float4* wcrow = s_wc + c * 8;
                #pragma unroll
                for (int q = 0; q < 8; q++) {
                    const float4 v = wcrow[q];
                    a = fmaf(rg[4*q],   v.x, a);
                    a = fmaf(rg[4*q+1], v.y, a);
                    a = fmaf(rg[4*q+2], v.z, a);
                    a = fmaf(rg[4*q+3], v.w, a);
                }
                out[4 * ii + c] = 1.f / (1.f + expf(-a));
            }
        }
    } else if (qt == 1) {
        #pragma unroll
        for (int s = 0; s < 2; s++) {
            float* r = s ? r1 : r0;
            const int ii = ib + (s ? p1 : p0);
            float2 a2 = make_float2(0.f, 0.f);
            #pragma unroll
            for (int q = 0; q < 16; q++) {
                const float4 v = s_wd[q];
                const float4 aq = *(const float4*)(r + 4*q);
                a2 = ffma2(make_float2(aq.x, aq.y), make_float2(v.x, v.y), a2);
                a2 = ffma2(make_float2(aq.z, aq.w), make_float2(v.z, v.w), a2);
            }
            const float xd = a2.x + a2.y + s_bd[0];
            out[4 * ii + 3] = fmaxf(xd, 0.f) + log1pf(expf(-fabsf(xd)));
        }
    }
}

extern "C" void kernel_launch(void* const* d_in, const int* in_sizes, int n_in,
                              void* d_out, int out_size) {
    (void)in_sizes; (void)n_in; (void)out_size;
    const float*  pos = (const float*)d_in[0];
    const float*  dir = (const float*)d_in[1];
    const float2* tab = (const float2*)d_in[2];
    const float *w0 = (const float*)d_in[3],  *b0 = (const float*)d_in[4];
    const float *w1 = (const float*)d_in[5],  *b1 = (const float*)d_in[6];
    const float *w2 = (const float*)d_in[7],  *b2 = (const float*)d_in[8];
    const float *wr = (const float*)d_in[9],  *br = (const float*)d_in[10];
    const float *wc = (const float*)d_in[11], *bc = (const float*)d_in[12];
    const float *wd = (const float*)d_in[13], *bd = (const float*)d_in[14];
    float* out = (float*)d_out;

    encode_kernel<<<(16 * N_PTS) / 256, 256>>>(pos, tab);

    cudaFuncSetAttribute(mlp_kernel,
                         cudaFuncAttributeMaxDynamicSharedMemorySize, SMEM_BYTES);
    mlp_kernel<<<N_PTS / PPB, BLOCK, SMEM_BYTES>>>(
        dir, w0, b0, w1, b1, w2, b2, wr, br, wc, bc, wd, bd, out);
}